// round 6
// baseline (speedup 1.0000x reference)
#include <cuda_runtime.h>
#include <cstdint>

// Problem constants: N=4096, D=128, S=32768, NUM_CLASS=500000.
#define DIM 128
#define MAX_S 32768
#define MAX_N 4096
#define NUM_CLASS_MAX 500000

// Scratch: tf32-pre-rounded operands + gathered bias.
static __device__ float g_w[(size_t)MAX_S * DIM];
static __device__ float g_x[(size_t)MAX_N * DIM];
static __device__ float g_bias[MAX_S];
static __device__ int g_ids_is64;

__device__ __forceinline__ uint32_t f2tf32(float f) {
    uint32_t u;
    asm("cvt.rna.tf32.f32 %0, %1;" : "=r"(u) : "f"(f));
    return u;
}

// ---------------------------------------------------------------------------
// Kernel 0: detect sample_ids dtype (int32 vs int64).
// ---------------------------------------------------------------------------
__global__ void detect_ids_kernel(const void* __restrict__ ids, int S) {
    __shared__ int ok;
    if (threadIdx.x == 0) ok = 1;
    __syncthreads();
    const long long* p = (const long long*)ids;
    int n64 = S / 2;
    for (int s = threadIdx.x; s < n64; s += blockDim.x) {
        long long v = p[s];
        if (v < 0 || v >= NUM_CLASS_MAX) ok = 0;
    }
    __syncthreads();
    if (threadIdx.x == 0) g_ids_is64 = ok;
}

__device__ __forceinline__ long long read_id(const void* ids, int s) {
    long long id = g_ids_is64 ? ((const long long*)ids)[s]
                              : (long long)((const int*)ids)[s];
    if (id < 0 || id >= NUM_CLASS_MAX) id = 0;
    return id;
}

// ---------------------------------------------------------------------------
// Kernel 1: gather weight[ids] -> g_w (tf32-rounded), bias[ids] -> g_bias.
// ---------------------------------------------------------------------------
__global__ void gather_kernel(const float* __restrict__ w,
                              const float* __restrict__ bias,
                              const void* __restrict__ ids,
                              int S) {
    int warp = (blockIdx.x * blockDim.x + threadIdx.x) >> 5;
    int lane = threadIdx.x & 31;
    int nwarps = (gridDim.x * blockDim.x) >> 5;
    for (int s = warp; s < S; s += nwarps) {
        long long id = read_id(ids, s);
        const float4* src = (const float4*)(w + (size_t)id * DIM);
        float4 v = src[lane];
        float4 o;
        o.x = __uint_as_float(f2tf32(v.x));
        o.y = __uint_as_float(f2tf32(v.y));
        o.z = __uint_as_float(f2tf32(v.z));
        o.w = __uint_as_float(f2tf32(v.w));
        ((float4*)(g_w + (size_t)s * DIM))[lane] = o;
        if (lane == 0) g_bias[s] = bias[id];
    }
}

// ---------------------------------------------------------------------------
// Kernel 1b: pre-round x into g_x (tf32).
// ---------------------------------------------------------------------------
__global__ void convert_x_kernel(const float* __restrict__ x, int total_f4) {
    int i = blockIdx.x * blockDim.x + threadIdx.x;
    int stride = gridDim.x * blockDim.x;
    for (; i < total_f4; i += stride) {
        float4 v = ((const float4*)x)[i];
        float4 o;
        o.x = __uint_as_float(f2tf32(v.x));
        o.y = __uint_as_float(f2tf32(v.y));
        o.z = __uint_as_float(f2tf32(v.z));
        o.w = __uint_as_float(f2tf32(v.w));
        ((float4*)g_x)[i] = o;
    }
}

// ---------------------------------------------------------------------------
// Kernel 2: tf32 GEMM  out[n][s] = dot(g_x[n,:], g_w[s,:]) + g_bias[s]
// BM=128, BN=256, BK=32, 256 threads (8 warps, 2x4), warp tile 64x64.
// All 4 K-chunks resident in smem (192KB, 1 CTA/SM); progressive cp.async
// group drain so compute(chunk0) overlaps loads of chunks 1-3.
// XOR-swizzled stage layout: rows of 32 floats, f4slot ^= (row & 7).
// ---------------------------------------------------------------------------
#define BM 128
#define BN 256
#define BK 32
#define NCHUNK (DIM / BK)            // 4
#define STAGE_F ((BM + BN) * BK)     // floats per chunk-stage = 12288 (48KB)

__device__ __forceinline__ void mma_tf32(float c[4], const uint32_t a[4],
                                         const uint32_t b[2]) {
    asm volatile(
        "mma.sync.aligned.m16n8k8.row.col.f32.tf32.tf32.f32 "
        "{%0,%1,%2,%3}, {%4,%5,%6,%7}, {%8,%9}, {%0,%1,%2,%3};\n"
        : "+f"(c[0]), "+f"(c[1]), "+f"(c[2]), "+f"(c[3])
        : "r"(a[0]), "r"(a[1]), "r"(a[2]), "r"(a[3]), "r"(b[0]), "r"(b[1]));
}

__device__ __forceinline__ void cp_async16(uint32_t smem_addr, const void* gptr) {
    asm volatile("cp.async.cg.shared.global [%0], [%1], 16;\n"
                 :: "r"(smem_addr), "l"(gptr));
}
__device__ __forceinline__ void cp_commit() {
    asm volatile("cp.async.commit_group;\n");
}

__device__ __forceinline__ void st_cs_f2(float* p, float a, float b) {
    asm volatile("st.global.cs.v2.f32 [%0], {%1,%2};\n"
                 :: "l"(p), "f"(a), "f"(b) : "memory");
}

// swizzled float index within a chunk-stage tile (rows of BK=32 floats)
__device__ __forceinline__ int swz(int row, int k4, int kin) {
    return row * BK + (((k4) ^ (row & 7)) << 2) + kin;
}

__global__ __launch_bounds__(256, 1)
void gemm_tf32_kernel(float* __restrict__ out, int N, int S) {
    extern __shared__ float sm[];
    const int tid  = threadIdx.x;
    const int lane = tid & 31;
    const int wid  = tid >> 5;
    const int wm   = wid & 1;        // 2 warp rows of 64
    const int wn   = wid >> 1;       // 4 warp cols of 64
    const int gid  = lane >> 2;      // 0..7
    const int tg   = lane & 3;       // 0..3

    const int m0 = blockIdx.x * BM;  // x = M tiles for B-tile L2 locality
    const int n0 = blockIdx.y * BN;

    uint32_t sbase;
    asm("{ .reg .u64 t; cvta.to.shared.u64 t, %1; cvt.u32.u64 %0, t; }"
        : "=r"(sbase) : "l"(sm));

    // ---- prefetch all 4 K-chunks, one commit group each ----
#pragma unroll
    for (int ch = 0; ch < NCHUNK; ch++) {
        const int k0 = ch * BK;
        uint32_t abase = sbase + (uint32_t)(ch * STAGE_F) * 4u;
        uint32_t bbase = abase + (uint32_t)(BM * BK) * 4u;
        // A: 128x32 = 1024 f4, 4 per thread
#pragma unroll
        for (int i = 0; i < 4; i++) {
            int f = tid + i * 256;
            int row = f >> 3, col = f & 7;
            uint32_t dst = abase + (uint32_t)((row * 8 + (col ^ (row & 7))) * 16);
            cp_async16(dst, g_x + (size_t)(m0 + row) * DIM + k0 + col * 4);
        }
        // B: 256x32 = 2048 f4, 8 per thread
#pragma unroll
        for (int i = 0; i < 8; i++) {
            int f = tid + i * 256;
            int row = f >> 3, col = f & 7;
            uint32_t dst = bbase + (uint32_t)((row * 8 + (col ^ (row & 7))) * 16);
            cp_async16(dst, g_w + (size_t)(n0 + row) * DIM + k0 + col * 4);
        }
        cp_commit();
    }

    float c[4][8][4];
#pragma unroll
    for (int mi = 0; mi < 4; mi++)
#pragma unroll
        for (int ni = 0; ni < 8; ni++)
#pragma unroll
            for (int j = 0; j < 4; j++) c[mi][ni][j] = 0.0f;

    // ---- compute chunks as their groups land ----
#pragma unroll
    for (int ch = 0; ch < NCHUNK; ch++) {
        switch (NCHUNK - 1 - ch) {
            case 3: asm volatile("cp.async.wait_group 3;\n"); break;
            case 2: asm volatile("cp.async.wait_group 2;\n"); break;
            case 1: asm volatile("cp.async.wait_group 1;\n"); break;
            default: asm volatile("cp.async.wait_group 0;\n"); break;
        }
        __syncthreads();
        const float* A = sm + ch * STAGE_F;
        const float* B = A + BM * BK;
#pragma unroll
        for (int kk = 0; kk < BK; kk += 8) {
            const int k4 = kk >> 2;
            uint32_t a[4][4], b[8][2];
#pragma unroll
            for (int mi = 0; mi < 4; mi++) {
                int rb = wm * 64 + mi * 16 + gid;     // rb & 7 == gid
                a[mi][0] = __float_as_uint(A[swz(rb,     k4,     tg)]);
                a[mi][1] = __float_as_uint(A[swz(rb + 8, k4,     tg)]);
                a[mi][2] = __float_as_uint(A[swz(rb,     k4 + 1, tg)]);
                a[mi][3] = __float_as_uint(A[swz(rb + 8, k4 + 1, tg)]);
            }
#pragma unroll
            for (int ni = 0; ni < 8; ni++) {
                int cb = wn * 64 + ni * 8 + gid;      // cb & 7 == gid
                b[ni][0] = __float_as_uint(B[swz(cb, k4,     tg)]);
                b[ni][1] = __float_as_uint(B[swz(cb, k4 + 1, tg)]);
            }
#pragma unroll
            for (int mi = 0; mi < 4; mi++)
#pragma unroll
                for (int ni = 0; ni < 8; ni++)
                    mma_tf32(c[mi][ni], a[mi], b[ni]);
        }
    }

    // ---- epilogue: bias add + streaming (.cs) float2 stores ----
#pragma unroll
    for (int mi = 0; mi < 4; mi++) {
        int r0 = m0 + wm * 64 + mi * 16 + gid;
#pragma unroll
        for (int ni = 0; ni < 8; ni++) {
            int col = n0 + wn * 64 + ni * 8 + 2 * tg;
            float b0 = g_bias[col];
            float b1 = g_bias[col + 1];
            st_cs_f2(out + (size_t)r0 * S + col,
                     c[mi][ni][0] + b0, c[mi][ni][1] + b1);
            st_cs_f2(out + (size_t)(r0 + 8) * S + col,
                     c[mi][ni][2] + b0, c[mi][ni][3] + b1);
        }
    }
}

// ---------------------------------------------------------------------------
// Kernel 3: pass-through sample_ids after the logits block.
// ---------------------------------------------------------------------------
__global__ void write_ids_kernel(const void* __restrict__ ids, void* out,
                                 long long base, long long extra, int S) {
    int s = blockIdx.x * blockDim.x + threadIdx.x;
    if (s >= S) return;
    long long id = read_id(ids, s);
    if (extra >= 2LL * S) {
        long long* p = (long long*)((float*)out + base);
        p[s] = id;
    } else if (extra >= (long long)S) {
        ((float*)out)[base + s] = (float)id;
    }
}

// ---------------------------------------------------------------------------
extern "C" void kernel_launch(void* const* d_in, const int* in_sizes, int n_in,
                              void* d_out, int out_size) {
    const float* x    = (const float*)d_in[0];
    const float* w    = (const float*)d_in[1];
    const float* bias = (const float*)d_in[2];
    const void*  ids  = d_in[3];

    const int N = in_sizes[0] / DIM;   // 4096
    const int S = in_sizes[3];         // 32768

    detect_ids_kernel<<<1, 256>>>(ids, S);
    gather_kernel<<<256, 256>>>(w, bias, ids, S);
    convert_x_kernel<<<128, 256>>>(x, N * (DIM / 4));

    static int smem_set = 0;
    if (!smem_set) {
        cudaFuncSetAttribute(gemm_tf32_kernel,
                             cudaFuncAttributeMaxDynamicSharedMemorySize,
                             NCHUNK * STAGE_F * (int)sizeof(float));
        smem_set = 1;
    }
    dim3 grid(N / BM, S / BN);
    gemm_tf32_kernel<<<grid, 256, NCHUNK * STAGE_F * sizeof(float)>>>(
        (float*)d_out, N, S);

    long long base  = (long long)N * (long long)S;
    long long extra = (long long)out_size - base;
    if (extra > 0) {
        write_ids_kernel<<<(S + 255) / 256, 256>>>(ids, d_out, base, extra, S);
    }
}

// round 7
// speedup vs baseline: 1.5389x; 1.5389x over previous
#include <cuda_runtime.h>
#include <cuda_fp16.h>
#include <cstdint>

// Problem constants: N=4096, D=128, S=32768, NUM_CLASS=500000.
#define DIM 128
#define MAX_S 32768
#define MAX_N 4096
#define NUM_CLASS_MAX 500000

// Scratch: fp16 operands + gathered fp32 bias.
static __device__ __half g_w[(size_t)MAX_S * DIM];
static __device__ __half g_x[(size_t)MAX_N * DIM];
static __device__ float g_bias[MAX_S];
static __device__ int g_ids_is64;

// ---------------------------------------------------------------------------
// Kernel 0: detect sample_ids dtype (int32 vs int64).
// ---------------------------------------------------------------------------
__global__ void detect_ids_kernel(const void* __restrict__ ids, int S) {
    __shared__ int ok;
    if (threadIdx.x == 0) ok = 1;
    __syncthreads();
    const long long* p = (const long long*)ids;
    int n64 = S / 2;
    for (int s = threadIdx.x; s < n64; s += blockDim.x) {
        long long v = p[s];
        if (v < 0 || v >= NUM_CLASS_MAX) ok = 0;
    }
    __syncthreads();
    if (threadIdx.x == 0) g_ids_is64 = ok;
}

__device__ __forceinline__ long long read_id(const void* ids, int s) {
    long long id = g_ids_is64 ? ((const long long*)ids)[s]
                              : (long long)((const int*)ids)[s];
    if (id < 0 || id >= NUM_CLASS_MAX) id = 0;
    return id;
}

// ---------------------------------------------------------------------------
// Kernel 1: gather weight[ids] -> g_w (fp16), bias[ids] -> g_bias.
// One warp per row: 32 lanes x float4 -> 4 halves each.
// ---------------------------------------------------------------------------
__global__ void gather_kernel(const float* __restrict__ w,
                              const float* __restrict__ bias,
                              const void* __restrict__ ids,
                              int S) {
    int warp = (blockIdx.x * blockDim.x + threadIdx.x) >> 5;
    int lane = threadIdx.x & 31;
    int nwarps = (gridDim.x * blockDim.x) >> 5;
    for (int s = warp; s < S; s += nwarps) {
        long long id = read_id(ids, s);
        float4 v = ((const float4*)(w + (size_t)id * DIM))[lane];
        __half2 h0 = __float22half2_rn(make_float2(v.x, v.y));
        __half2 h1 = __float22half2_rn(make_float2(v.z, v.w));
        __half2* dst = (__half2*)(g_w + (size_t)s * DIM) + lane * 2;
        dst[0] = h0;
        dst[1] = h1;
        if (lane == 0) g_bias[s] = bias[id];
    }
}

// ---------------------------------------------------------------------------
// Kernel 1b: convert x -> g_x (fp16).
// ---------------------------------------------------------------------------
__global__ void convert_x_kernel(const float* __restrict__ x, int total_f4) {
    int i = blockIdx.x * blockDim.x + threadIdx.x;
    int stride = gridDim.x * blockDim.x;
    for (; i < total_f4; i += stride) {
        float4 v = ((const float4*)x)[i];
        __half2 h0 = __float22half2_rn(make_float2(v.x, v.y));
        __half2 h1 = __float22half2_rn(make_float2(v.z, v.w));
        __half2* dst = (__half2*)g_x + i * 2;
        dst[0] = h0;
        dst[1] = h1;
    }
}

// ---------------------------------------------------------------------------
// Kernel 2: fp16 GEMM  out[n][s] = dot(g_x[n,:], g_w[s,:]) + g_bias[s]
// BM=128, BN=256, BK=64 halves, 512 threads (16 warps, 2x8), warp tile 64x32.
// Full K=128 resident in smem (2 x 48KB); progressive cp.async drain.
// Rows are 128B (64 halves); 16B-block XOR swizzle (blk ^ (row&7)) —
// conflict-free for cp.async fill and all fragment LDS.
// mma.sync.aligned.m16n8k16.row.col.f32.f16.f16.f32
// ---------------------------------------------------------------------------
#define BM 128
#define BN 256
#define BKH 64                             // halves per chunk
#define NCHUNK 2
#define A_CH_BYTES (BM * BKH * 2)          // 16384
#define B_CH_BYTES (BN * BKH * 2)          // 32768
#define CH_BYTES (A_CH_BYTES + B_CH_BYTES) // 49152
#define SM_TOTAL (NCHUNK * CH_BYTES)       // 98304

__device__ __forceinline__ void mma_f16(float c[4], const uint32_t a[4],
                                        const uint32_t b[2]) {
    asm volatile(
        "mma.sync.aligned.m16n8k16.row.col.f32.f16.f16.f32 "
        "{%0,%1,%2,%3}, {%4,%5,%6,%7}, {%8,%9}, {%0,%1,%2,%3};\n"
        : "+f"(c[0]), "+f"(c[1]), "+f"(c[2]), "+f"(c[3])
        : "r"(a[0]), "r"(a[1]), "r"(a[2]), "r"(a[3]), "r"(b[0]), "r"(b[1]));
}

__device__ __forceinline__ void cp_async16(uint32_t smem_addr, const void* gptr) {
    asm volatile("cp.async.cg.shared.global [%0], [%1], 16;\n"
                 :: "r"(smem_addr), "l"(gptr));
}
__device__ __forceinline__ void cp_commit() {
    asm volatile("cp.async.commit_group;\n");
}
__device__ __forceinline__ void st_cs_f2(float* p, float a, float b) {
    asm volatile("st.global.cs.v2.f32 [%0], {%1,%2};\n"
                 :: "l"(p), "f"(a), "f"(b) : "memory");
}

__global__ __launch_bounds__(512, 1)
void gemm_f16_kernel(float* __restrict__ out, int N, int S) {
    extern __shared__ char sm[];
    const int tid  = threadIdx.x;
    const int lane = tid & 31;
    const int wid  = tid >> 5;
    const int wm   = wid & 1;        // 2 warp rows of 64
    const int wn   = wid >> 1;       // 8 warp cols of 32
    const int gid  = lane >> 2;      // 0..7
    const int tg   = lane & 3;       // 0..3

    const int m0 = blockIdx.x * BM;  // x = M tiles for B-tile L2 locality
    const int n0 = blockIdx.y * BN;

    uint32_t sbase;
    asm("{ .reg .u64 t; cvta.to.shared.u64 t, %1; cvt.u32.u64 %0, t; }"
        : "=r"(sbase) : "l"(sm));

    // ---- prefetch both K-chunks, one commit group each ----
#pragma unroll
    for (int ch = 0; ch < NCHUNK; ch++) {
        const int k0 = ch * BKH;
        uint32_t abase = sbase + (uint32_t)(ch * CH_BYTES);
        uint32_t bbase = abase + A_CH_BYTES;
        // A: 128 rows x 8 16B blocks = 1024 ops, 2 per thread
#pragma unroll
        for (int i = 0; i < 2; i++) {
            int f = tid + i * 512;
            int r = f >> 3, q = f & 7;
            uint32_t dst = abase + (uint32_t)(r * 128 + ((q ^ (r & 7)) << 4));
            cp_async16(dst, g_x + (size_t)(m0 + r) * DIM + k0 + q * 8);
        }
        // B: 256 rows x 8 blocks = 2048 ops, 4 per thread
#pragma unroll
        for (int i = 0; i < 4; i++) {
            int f = tid + i * 512;
            int r = f >> 3, q = f & 7;
            uint32_t dst = bbase + (uint32_t)(r * 128 + ((q ^ (r & 7)) << 4));
            cp_async16(dst, g_w + (size_t)(n0 + r) * DIM + k0 + q * 8);
        }
        cp_commit();
    }

    float c[4][4][4];
#pragma unroll
    for (int mi = 0; mi < 4; mi++)
#pragma unroll
        for (int ni = 0; ni < 4; ni++)
#pragma unroll
            for (int j = 0; j < 4; j++) c[mi][ni][j] = 0.0f;

    // ---- compute chunks as their groups land ----
#pragma unroll
    for (int ch = 0; ch < NCHUNK; ch++) {
        if (ch == 0) asm volatile("cp.async.wait_group 1;\n");
        else         asm volatile("cp.async.wait_group 0;\n");
        __syncthreads();
        const char* A = sm + ch * CH_BYTES;
        const char* B = A + A_CH_BYTES;
#pragma unroll
        for (int ks = 0; ks < 4; ks++) {          // 4 k16-steps per chunk
            uint32_t a[4][4], b[4][2];
#pragma unroll
            for (int mi = 0; mi < 4; mi++) {
                int rb = wm * 64 + mi * 16 + gid;             // rb&7 == gid
                const char* r0 = A + rb * 128;
                const char* r1 = A + (rb + 8) * 128;
                int o0 = (((ks * 2)     ^ gid) << 4) + tg * 4;
                int o1 = (((ks * 2 + 1) ^ gid) << 4) + tg * 4;
                a[mi][0] = *(const uint32_t*)(r0 + o0);
                a[mi][1] = *(const uint32_t*)(r1 + o0);
                a[mi][2] = *(const uint32_t*)(r0 + o1);
                a[mi][3] = *(const uint32_t*)(r1 + o1);
            }
#pragma unroll
            for (int ni = 0; ni < 4; ni++) {
                int cb = wn * 32 + ni * 8 + gid;              // cb&7 == gid
                const char* r = B + cb * 128;
                int o0 = (((ks * 2)     ^ gid) << 4) + tg * 4;
                int o1 = (((ks * 2 + 1) ^ gid) << 4) + tg * 4;
                b[ni][0] = *(const uint32_t*)(r + o0);
                b[ni][1] = *(const uint32_t*)(r + o1);
            }
#pragma unroll
            for (int mi = 0; mi < 4; mi++)
#pragma unroll
                for (int ni = 0; ni < 4; ni++)
                    mma_f16(c[mi][ni], a[mi], b[ni]);
        }
    }

    // ---- epilogue: bias add + streaming (.cs) float2 stores ----
#pragma unroll
    for (int mi = 0; mi < 4; mi++) {
        int r0 = m0 + wm * 64 + mi * 16 + gid;
#pragma unroll
        for (int ni = 0; ni < 4; ni++) {
            int col = n0 + wn * 32 + ni * 8 + 2 * tg;
            float b0 = g_bias[col];
            float b1 = g_bias[col + 1];
            st_cs_f2(out + (size_t)r0 * S + col,
                     c[mi][ni][0] + b0, c[mi][ni][1] + b1);
            st_cs_f2(out + (size_t)(r0 + 8) * S + col,
                     c[mi][ni][2] + b0, c[mi][ni][3] + b1);
        }
    }
}

// ---------------------------------------------------------------------------
// Kernel 3: pass-through sample_ids after the logits block.
// ---------------------------------------------------------------------------
__global__ void write_ids_kernel(const void* __restrict__ ids, void* out,
                                 long long base, long long extra, int S) {
    int s = blockIdx.x * blockDim.x + threadIdx.x;
    if (s >= S) return;
    long long id = read_id(ids, s);
    if (extra >= 2LL * S) {
        long long* p = (long long*)((float*)out + base);
        p[s] = id;
    } else if (extra >= (long long)S) {
        ((float*)out)[base + s] = (float)id;
    }
}

// ---------------------------------------------------------------------------
extern "C" void kernel_launch(void* const* d_in, const int* in_sizes, int n_in,
                              void* d_out, int out_size) {
    const float* x    = (const float*)d_in[0];
    const float* w    = (const float*)d_in[1];
    const float* bias = (const float*)d_in[2];
    const void*  ids  = d_in[3];

    const int N = in_sizes[0] / DIM;   // 4096
    const int S = in_sizes[3];         // 32768

    detect_ids_kernel<<<1, 256>>>(ids, S);
    gather_kernel<<<256, 256>>>(w, bias, ids, S);
    convert_x_kernel<<<128, 256>>>(x, N * (DIM / 4));

    static int smem_set = 0;
    if (!smem_set) {
        cudaFuncSetAttribute(gemm_f16_kernel,
                             cudaFuncAttributeMaxDynamicSharedMemorySize,
                             SM_TOTAL);
        smem_set = 1;
    }
    dim3 grid(N / BM, S / BN);
    gemm_f16_kernel<<<grid, 512, SM_TOTAL>>>((float*)d_out, N, S);

    long long base  = (long long)N * (long long)S;
    long long extra = (long long)out_size - base;
    if (extra > 0) {
        write_ids_kernel<<<(S + 255) / 256, 256>>>(ids, d_out, base, extra, S);
    }
}

// round 8
// speedup vs baseline: 1.5786x; 1.0258x over previous
#include <cuda_runtime.h>
#include <cuda_fp16.h>
#include <cstdint>

// Problem constants: N=4096, D=128, S=32768, NUM_CLASS=500000.
#define DIM 128
#define MAX_S 32768
#define MAX_N 4096
#define NUM_CLASS_MAX 500000

// Scratch: fp16 operands + gathered fp32 bias.
static __device__ __half g_w[(size_t)MAX_S * DIM];
static __device__ __half g_x[(size_t)MAX_N * DIM];
static __device__ float g_bias[MAX_S];
static __device__ int g_ids_is64;

// ---------------------------------------------------------------------------
// Kernel 0: detect sample_ids dtype (int32 vs int64).
// ---------------------------------------------------------------------------
__global__ void detect_ids_kernel(const void* __restrict__ ids, int S) {
    __shared__ int ok;
    if (threadIdx.x == 0) ok = 1;
    __syncthreads();
    const long long* p = (const long long*)ids;
    int n64 = S / 2;
    for (int s = threadIdx.x; s < n64; s += blockDim.x) {
        long long v = p[s];
        if (v < 0 || v >= NUM_CLASS_MAX) ok = 0;
    }
    __syncthreads();
    if (threadIdx.x == 0) g_ids_is64 = ok;
}

__device__ __forceinline__ long long read_id(const void* ids, int s) {
    long long id = g_ids_is64 ? ((const long long*)ids)[s]
                              : (long long)((const int*)ids)[s];
    if (id < 0 || id >= NUM_CLASS_MAX) id = 0;
    return id;
}

// ---------------------------------------------------------------------------
// Kernel 1: gather weight[ids] -> g_w (fp16), bias[ids] -> g_bias.
// ---------------------------------------------------------------------------
__global__ void gather_kernel(const float* __restrict__ w,
                              const float* __restrict__ bias,
                              const void* __restrict__ ids,
                              int S) {
    int warp = (blockIdx.x * blockDim.x + threadIdx.x) >> 5;
    int lane = threadIdx.x & 31;
    int nwarps = (gridDim.x * blockDim.x) >> 5;
    for (int s = warp; s < S; s += nwarps) {
        long long id = read_id(ids, s);
        float4 v = ((const float4*)(w + (size_t)id * DIM))[lane];
        __half2 h0 = __float22half2_rn(make_float2(v.x, v.y));
        __half2 h1 = __float22half2_rn(make_float2(v.z, v.w));
        __half2* dst = (__half2*)(g_w + (size_t)s * DIM) + lane * 2;
        dst[0] = h0;
        dst[1] = h1;
        if (lane == 0) g_bias[s] = bias[id];
    }
}

// ---------------------------------------------------------------------------
// Kernel 1b: convert x -> g_x (fp16).
// ---------------------------------------------------------------------------
__global__ void convert_x_kernel(const float* __restrict__ x, int total_f4) {
    int i = blockIdx.x * blockDim.x + threadIdx.x;
    int stride = gridDim.x * blockDim.x;
    for (; i < total_f4; i += stride) {
        float4 v = ((const float4*)x)[i];
        __half2 h0 = __float22half2_rn(make_float2(v.x, v.y));
        __half2 h1 = __float22half2_rn(make_float2(v.z, v.w));
        __half2* dst = (__half2*)g_x + i * 2;
        dst[0] = h0;
        dst[1] = h1;
    }
}

// ---------------------------------------------------------------------------
// Kernel 2: fp16 GEMM via mma.m16n8k16 + ldmatrix fragment loads.
// BM=128, BN=256, BK=64 halves, 512 threads (16 warps, 2x8), warp tile 64x32.
// Full K=128 resident in smem (2 x 48KB chunks); progressive cp.async drain.
// Rows are 128B (64 halves); 16B-block XOR swizzle (blk ^ (row&7)).
// ---------------------------------------------------------------------------
#define BM 128
#define BN 256
#define BKH 64                             // halves per chunk
#define NCHUNK 2
#define A_CH_BYTES (BM * BKH * 2)          // 16384
#define B_CH_BYTES (BN * BKH * 2)          // 32768
#define CH_BYTES (A_CH_BYTES + B_CH_BYTES) // 49152
#define SM_TOTAL (NCHUNK * CH_BYTES)       // 98304

__device__ __forceinline__ void mma_f16(float c[4], const uint32_t a[4],
                                        const uint32_t b[2]) {
    asm volatile(
        "mma.sync.aligned.m16n8k16.row.col.f32.f16.f16.f32 "
        "{%0,%1,%2,%3}, {%4,%5,%6,%7}, {%8,%9}, {%0,%1,%2,%3};\n"
        : "+f"(c[0]), "+f"(c[1]), "+f"(c[2]), "+f"(c[3])
        : "r"(a[0]), "r"(a[1]), "r"(a[2]), "r"(a[3]), "r"(b[0]), "r"(b[1]));
}

__device__ __forceinline__ void ldsm_x4(uint32_t* r, uint32_t addr) {
    asm volatile(
        "ldmatrix.sync.aligned.m8n8.x4.shared.b16 {%0,%1,%2,%3}, [%4];"
        : "=r"(r[0]), "=r"(r[1]), "=r"(r[2]), "=r"(r[3]) : "r"(addr));
}

__device__ __forceinline__ void cp_async16(uint32_t smem_addr, const void* gptr) {
    asm volatile("cp.async.cg.shared.global [%0], [%1], 16;\n"
                 :: "r"(smem_addr), "l"(gptr));
}
__device__ __forceinline__ void cp_commit() {
    asm volatile("cp.async.commit_group;\n");
}
__device__ __forceinline__ void st_cs_f2(float* p, float a, float b) {
    asm volatile("st.global.cs.v2.f32 [%0], {%1,%2};\n"
                 :: "l"(p), "f"(a), "f"(b) : "memory");
}

__global__ __launch_bounds__(512, 1)
void gemm_f16_kernel(float* __restrict__ out, int N, int S) {
    extern __shared__ char sm[];
    const int tid  = threadIdx.x;
    const int lane = tid & 31;
    const int wid  = tid >> 5;
    const int wm   = wid & 1;        // 2 warp rows of 64
    const int wn   = wid >> 1;       // 8 warp cols of 32
    const int gid  = lane >> 2;      // 0..7
    const int tg   = lane & 3;       // 0..3

    const int m0 = blockIdx.x * BM;  // x = M tiles for B-tile L2 locality
    const int n0 = blockIdx.y * BN;

    uint32_t sbase;
    asm("{ .reg .u64 t; cvta.to.shared.u64 t, %1; cvt.u32.u64 %0, t; }"
        : "=r"(sbase) : "l"(sm));

    // ---- prefetch both K-chunks, one commit group each ----
#pragma unroll
    for (int ch = 0; ch < NCHUNK; ch++) {
        const int k0 = ch * BKH;
        uint32_t abase = sbase + (uint32_t)(ch * CH_BYTES);
        uint32_t bbase = abase + A_CH_BYTES;
#pragma unroll
        for (int i = 0; i < 2; i++) {       // A: 128 rows x 8 blocks
            int f = tid + i * 512;
            int r = f >> 3, q = f & 7;
            uint32_t dst = abase + (uint32_t)(r * 128 + ((q ^ (r & 7)) << 4));
            cp_async16(dst, g_x + (size_t)(m0 + r) * DIM + k0 + q * 8);
        }
#pragma unroll
        for (int i = 0; i < 4; i++) {       // B: 256 rows x 8 blocks
            int f = tid + i * 512;
            int r = f >> 3, q = f & 7;
            uint32_t dst = bbase + (uint32_t)(r * 128 + ((q ^ (r & 7)) << 4));
            cp_async16(dst, g_w + (size_t)(n0 + r) * DIM + k0 + q * 8);
        }
        cp_commit();
    }

    float c[4][4][4];
#pragma unroll
    for (int mi = 0; mi < 4; mi++)
#pragma unroll
        for (int ni = 0; ni < 4; ni++)
#pragma unroll
            for (int j = 0; j < 4; j++) c[mi][ni][j] = 0.0f;

    // ---- ldmatrix per-lane row assignments ----
    // A x4: matrix idx = lane>>3: {0: rows rb+l&7 blkE, 1: rb+8+l&7 blkE,
    //                              2: rb+l&7 blkO, 3: rb+8+l&7 blkO}
    //   -> row = rb + (lane&15), sel = lane>>4  (order a0..a3 matches mma A)
    const int rowA = (lane & 15);
    const int selA = (lane >> 4) & 1;
    // B x4: {0: cb+l&7 blkE, 1: cb+l&7 blkO, 2: cb+8+l&7 blkE, 3: cb+8 blkO}
    //   -> row = cb + (lane&7) + ((lane&16)>>1), sel = (lane>>3)&1
    const int rowB = (lane & 7) + ((lane & 16) >> 1);
    const int selB = (lane >> 3) & 1;
    const int swzA = rowA & 7;           // XOR operand (rb % 16 == 0)
    const int swzB = rowB & 7;           // (cb % 16 == 0)

    // ---- compute chunks as their groups land ----
#pragma unroll
    for (int ch = 0; ch < NCHUNK; ch++) {
        if (ch == 0) asm volatile("cp.async.wait_group 1;\n");
        else         asm volatile("cp.async.wait_group 0;\n");
        __syncthreads();
        const uint32_t Ab = sbase + (uint32_t)(ch * CH_BYTES);
        const uint32_t Bb = Ab + A_CH_BYTES;
        uint32_t aAddr[4], bAddr[2];
#pragma unroll
        for (int mi = 0; mi < 4; mi++)
            aAddr[mi] = Ab + (uint32_t)((wm * 64 + mi * 16 + rowA) * 128);
#pragma unroll
        for (int nj = 0; nj < 2; nj++)
            bAddr[nj] = Bb + (uint32_t)((wn * 32 + nj * 16 + rowB) * 128);

#pragma unroll
        for (int ks = 0; ks < 4; ks++) {          // 4 k16-steps per chunk
            const uint32_t offA = (uint32_t)(((2 * ks + selA) ^ swzA) << 4);
            const uint32_t offB = (uint32_t)(((2 * ks + selB) ^ swzB) << 4);
            uint32_t a[4][4], b[2][4];
#pragma unroll
            for (int mi = 0; mi < 4; mi++)
                ldsm_x4(a[mi], aAddr[mi] + offA);
#pragma unroll
            for (int nj = 0; nj < 2; nj++)
                ldsm_x4(b[nj], bAddr[nj] + offB);
#pragma unroll
            for (int mi = 0; mi < 4; mi++) {
#pragma unroll
                for (int ni = 0; ni < 4; ni++)
                    mma_f16(c[mi][ni], a[mi], &b[ni >> 1][(ni & 1) * 2]);
            }
        }
    }

    // ---- epilogue: bias add + streaming (.cs) float2 stores ----
#pragma unroll
    for (int mi = 0; mi < 4; mi++) {
        int r0 = m0 + wm * 64 + mi * 16 + gid;
#pragma unroll
        for (int ni = 0; ni < 4; ni++) {
            int col = n0 + wn * 32 + ni * 8 + 2 * tg;
            float b0 = g_bias[col];
            float b1 = g_bias[col + 1];
            st_cs_f2(out + (size_t)r0 * S + col,
                     c[mi][ni][0] + b0, c[mi][ni][1] + b1);
            st_cs_f2(out + (size_t)(r0 + 8) * S + col,
                     c[mi][ni][2] + b0, c[mi][ni][3] + b1);
        }
    }
}

// ---------------------------------------------------------------------------
// Kernel 3: pass-through sample_ids after the logits block.
// ---------------------------------------------------------------------------
__global__ void write_ids_kernel(const void* __restrict__ ids, void* out,
                                 long long base, long long extra, int S) {
    int s = blockIdx.x * blockDim.x + threadIdx.x;
    if (s >= S) return;
    long long id = read_id(ids, s);
    if (extra >= 2LL * S) {
        long long* p = (long long*)((float*)out + base);
        p[s] = id;
    } else if (extra >= (long long)S) {
        ((float*)out)[base + s] = (float)id;
    }
}

// ---------------------------------------------------------------------------
extern "C" void kernel_launch(void* const* d_in, const int* in_sizes, int n_in,
                              void* d_out, int out_size) {
    const float* x    = (const float*)d_in[0];
    const float* w    = (const float*)d_in[1];
    const float* bias = (const float*)d_in[2];
    const void*  ids  = d_in[3];

    const int N = in_sizes[0] / DIM;   // 4096
    const int S = in_sizes[3];         // 32768

    detect_ids_kernel<<<1, 256>>>(ids, S);
    gather_kernel<<<256, 256>>>(w, bias, ids, S);
    convert_x_kernel<<<128, 256>>>(x, N * (DIM / 4));

    static int smem_set = 0;
    if (!smem_set) {
        cudaFuncSetAttribute(gemm_f16_kernel,
                             cudaFuncAttributeMaxDynamicSharedMemorySize,
                             SM_TOTAL);
        smem_set = 1;
    }
    dim3 grid(N / BM, S / BN);
    gemm_f16_kernel<<<grid, 512, SM_TOTAL>>>((float*)d_out, N, S);

    long long base  = (long long)N * (long long)S;
    long long extra = (long long)out_size - base;
    if (extra > 0) {
        write_ids_kernel<<<(S + 255) / 256, 256>>>(ids, d_out, base, extra, S);
    }
}

// round 9
// speedup vs baseline: 1.7931x; 1.1359x over previous
#include <cuda_runtime.h>
#include <cuda_fp16.h>
#include <cstdint>

// Problem constants: N=4096, D=128, S=32768, NUM_CLASS=500000.
#define DIM 128
#define MAX_S 32768
#define MAX_N 4096
#define NUM_CLASS_MAX 500000

// Scratch: fp16 operands + gathered fp32 bias.
static __device__ __half g_w[(size_t)MAX_S * DIM];
static __device__ __half g_x[(size_t)MAX_N * DIM];
static __device__ float g_bias[MAX_S];
static __device__ int g_ids_is64;

// ---------------------------------------------------------------------------
// Kernel 0: detect sample_ids dtype (int32 vs int64).
// ---------------------------------------------------------------------------
__global__ void detect_ids_kernel(const void* __restrict__ ids, int S) {
    __shared__ int ok;
    if (threadIdx.x == 0) ok = 1;
    __syncthreads();
    const long long* p = (const long long*)ids;
    int n64 = S / 2;
    for (int s = threadIdx.x; s < n64; s += blockDim.x) {
        long long v = p[s];
        if (v < 0 || v >= NUM_CLASS_MAX) ok = 0;
    }
    __syncthreads();
    if (threadIdx.x == 0) g_ids_is64 = ok;
}

__device__ __forceinline__ long long read_id(const void* ids, int s) {
    long long id = g_ids_is64 ? ((const long long*)ids)[s]
                              : (long long)((const int*)ids)[s];
    if (id < 0 || id >= NUM_CLASS_MAX) id = 0;
    return id;
}

// ---------------------------------------------------------------------------
// Kernel 1: gather weight[ids] -> g_w (fp16), bias[ids] -> g_bias.
// ---------------------------------------------------------------------------
__global__ void gather_kernel(const float* __restrict__ w,
                              const float* __restrict__ bias,
                              const void* __restrict__ ids,
                              int S) {
    int warp = (blockIdx.x * blockDim.x + threadIdx.x) >> 5;
    int lane = threadIdx.x & 31;
    int nwarps = (gridDim.x * blockDim.x) >> 5;
    for (int s = warp; s < S; s += nwarps) {
        long long id = read_id(ids, s);
        float4 v = ((const float4*)(w + (size_t)id * DIM))[lane];
        __half2 h0 = __float22half2_rn(make_float2(v.x, v.y));
        __half2 h1 = __float22half2_rn(make_float2(v.z, v.w));
        __half2* dst = (__half2*)(g_w + (size_t)s * DIM) + lane * 2;
        dst[0] = h0;
        dst[1] = h1;
        if (lane == 0) g_bias[s] = bias[id];
    }
}

// ---------------------------------------------------------------------------
// Kernel 1b: convert x -> g_x (fp16).
// ---------------------------------------------------------------------------
__global__ void convert_x_kernel(const float* __restrict__ x, int total_f4) {
    int i = blockIdx.x * blockDim.x + threadIdx.x;
    int stride = gridDim.x * blockDim.x;
    for (; i < total_f4; i += stride) {
        float4 v = ((const float4*)x)[i];
        __half2 h0 = __float22half2_rn(make_float2(v.x, v.y));
        __half2 h1 = __float22half2_rn(make_float2(v.z, v.w));
        __half2* dst = (__half2*)g_x + i * 2;
        dst[0] = h0;
        dst[1] = h1;
    }
}

// ---------------------------------------------------------------------------
// Kernel 2: fp16 GEMM via mma.m16n8k16 + ldmatrix fragment loads.
// BM=128, BN=128, BK=64 halves, 256 threads (8 warps, 2x4), warp tile 64x32.
// Full K=128 resident in smem (2 x 32KB chunks = 64KB) -> 2 CTAs/SM so
// prolog/epilogue of one CTA overlaps the mainloop of the other.
// Rows are 128B (64 halves); 16B-block XOR swizzle (blk ^ (row&7)).
// ---------------------------------------------------------------------------
#define BM 128
#define BN 128
#define BKH 64                             // halves per chunk
#define NCHUNK 2
#define A_CH_BYTES (BM * BKH * 2)          // 16384
#define B_CH_BYTES (BN * BKH * 2)          // 16384
#define CH_BYTES (A_CH_BYTES + B_CH_BYTES) // 32768
#define SM_TOTAL (NCHUNK * CH_BYTES)       // 65536

__device__ __forceinline__ void mma_f16(float c[4], const uint32_t a[4],
                                        const uint32_t b[2]) {
    asm volatile(
        "mma.sync.aligned.m16n8k16.row.col.f32.f16.f16.f32 "
        "{%0,%1,%2,%3}, {%4,%5,%6,%7}, {%8,%9}, {%0,%1,%2,%3};\n"
        : "+f"(c[0]), "+f"(c[1]), "+f"(c[2]), "+f"(c[3])
        : "r"(a[0]), "r"(a[1]), "r"(a[2]), "r"(a[3]), "r"(b[0]), "r"(b[1]));
}

__device__ __forceinline__ void ldsm_x4(uint32_t* r, uint32_t addr) {
    asm volatile(
        "ldmatrix.sync.aligned.m8n8.x4.shared.b16 {%0,%1,%2,%3}, [%4];"
        : "=r"(r[0]), "=r"(r[1]), "=r"(r[2]), "=r"(r[3]) : "r"(addr));
}

__device__ __forceinline__ void cp_async16(uint32_t smem_addr, const void* gptr) {
    asm volatile("cp.async.cg.shared.global [%0], [%1], 16;\n"
                 :: "r"(smem_addr), "l"(gptr));
}
__device__ __forceinline__ void cp_commit() {
    asm volatile("cp.async.commit_group;\n");
}
__device__ __forceinline__ void st_cs_f2(float* p, float a, float b) {
    asm volatile("st.global.cs.v2.f32 [%0], {%1,%2};\n"
                 :: "l"(p), "f"(a), "f"(b) : "memory");
}

__global__ __launch_bounds__(256, 2)
void gemm_f16_kernel(float* __restrict__ out, int N, int S) {
    extern __shared__ char sm[];
    const int tid  = threadIdx.x;
    const int lane = tid & 31;
    const int wid  = tid >> 5;
    const int wm   = wid & 1;        // 2 warp rows of 64
    const int wn   = wid >> 1;       // 4 warp cols of 32
    const int gid  = lane >> 2;      // 0..7
    const int tg   = lane & 3;       // 0..3

    const int m0 = blockIdx.x * BM;  // x = M tiles -> consecutive CTAs share B
    const int n0 = blockIdx.y * BN;

    uint32_t sbase;
    asm("{ .reg .u64 t; cvta.to.shared.u64 t, %1; cvt.u32.u64 %0, t; }"
        : "=r"(sbase) : "l"(sm));

    // ---- prefetch both K-chunks, one commit group each ----
#pragma unroll
    for (int ch = 0; ch < NCHUNK; ch++) {
        const int k0 = ch * BKH;
        uint32_t abase = sbase + (uint32_t)(ch * CH_BYTES);
        uint32_t bbase = abase + A_CH_BYTES;
#pragma unroll
        for (int i = 0; i < 4; i++) {       // A: 128 rows x 8 blocks = 1024
            int f = tid + i * 256;
            int r = f >> 3, q = f & 7;
            uint32_t dst = abase + (uint32_t)(r * 128 + ((q ^ (r & 7)) << 4));
            cp_async16(dst, g_x + (size_t)(m0 + r) * DIM + k0 + q * 8);
        }
#pragma unroll
        for (int i = 0; i < 4; i++) {       // B: 128 rows x 8 blocks = 1024
            int f = tid + i * 256;
            int r = f >> 3, q = f & 7;
            uint32_t dst = bbase + (uint32_t)(r * 128 + ((q ^ (r & 7)) << 4));
            cp_async16(dst, g_w + (size_t)(n0 + r) * DIM + k0 + q * 8);
        }
        cp_commit();
    }

    float c[4][4][4];
#pragma unroll
    for (int mi = 0; mi < 4; mi++)
#pragma unroll
        for (int ni = 0; ni < 4; ni++)
#pragma unroll
            for (int j = 0; j < 4; j++) c[mi][ni][j] = 0.0f;

    // ---- ldmatrix per-lane row assignments (same scheme as round 8) ----
    const int rowA = (lane & 15);
    const int selA = (lane >> 4) & 1;
    const int rowB = (lane & 7) + ((lane & 16) >> 1);
    const int selB = (lane >> 3) & 1;
    const int swzA = rowA & 7;
    const int swzB = rowB & 7;

    // ---- compute chunks as their groups land ----
#pragma unroll
    for (int ch = 0; ch < NCHUNK; ch++) {
        if (ch == 0) asm volatile("cp.async.wait_group 1;\n");
        else         asm volatile("cp.async.wait_group 0;\n");
        __syncthreads();
        const uint32_t Ab = sbase + (uint32_t)(ch * CH_BYTES);
        const uint32_t Bb = Ab + A_CH_BYTES;
        uint32_t aAddr[4], bAddr[2];
#pragma unroll
        for (int mi = 0; mi < 4; mi++)
            aAddr[mi] = Ab + (uint32_t)((wm * 64 + mi * 16 + rowA) * 128);
#pragma unroll
        for (int nj = 0; nj < 2; nj++)
            bAddr[nj] = Bb + (uint32_t)((wn * 32 + nj * 16 + rowB) * 128);

#pragma unroll
        for (int ks = 0; ks < 4; ks++) {          // 4 k16-steps per chunk
            const uint32_t offA = (uint32_t)(((2 * ks + selA) ^ swzA) << 4);
            const uint32_t offB = (uint32_t)(((2 * ks + selB) ^ swzB) << 4);
            uint32_t a[4][4], b[2][4];
#pragma unroll
            for (int mi = 0; mi < 4; mi++)
                ldsm_x4(a[mi], aAddr[mi] + offA);
#pragma unroll
            for (int nj = 0; nj < 2; nj++)
                ldsm_x4(b[nj], bAddr[nj] + offB);
#pragma unroll
            for (int mi = 0; mi < 4; mi++) {
#pragma unroll
                for (int ni = 0; ni < 4; ni++)
                    mma_f16(c[mi][ni], a[mi], &b[ni >> 1][(ni & 1) * 2]);
            }
        }
    }

    // ---- epilogue: bias add + streaming (.cs) float2 stores ----
#pragma unroll
    for (int mi = 0; mi < 4; mi++) {
        int r0 = m0 + wm * 64 + mi * 16 + gid;
#pragma unroll
        for (int ni = 0; ni < 4; ni++) {
            int col = n0 + wn * 32 + ni * 8 + 2 * tg;
            float b0 = g_bias[col];
            float b1 = g_bias[col + 1];
            st_cs_f2(out + (size_t)r0 * S + col,
                     c[mi][ni][0] + b0, c[mi][ni][1] + b1);
            st_cs_f2(out + (size_t)(r0 + 8) * S + col,
                     c[mi][ni][2] + b0, c[mi][ni][3] + b1);
        }
    }
}

// ---------------------------------------------------------------------------
// Kernel 3: pass-through sample_ids after the logits block.
// ---------------------------------------------------------------------------
__global__ void write_ids_kernel(const void* __restrict__ ids, void* out,
                                 long long base, long long extra, int S) {
    int s = blockIdx.x * blockDim.x + threadIdx.x;
    if (s >= S) return;
    long long id = read_id(ids, s);
    if (extra >= 2LL * S) {
        long long* p = (long long*)((float*)out + base);
        p[s] = id;
    } else if (extra >= (long long)S) {
        ((float*)out)[base + s] = (float)id;
    }
}

// ---------------------------------------------------------------------------
extern "C" void kernel_launch(void* const* d_in, const int* in_sizes, int n_in,
                              void* d_out, int out_size) {
    const float* x    = (const float*)d_in[0];
    const float* w    = (const float*)d_in[1];
    const float* bias = (const float*)d_in[2];
    const void*  ids  = d_in[3];

    const int N = in_sizes[0] / DIM;   // 4096
    const int S = in_sizes[3];         // 32768

    detect_ids_kernel<<<1, 256>>>(ids, S);
    gather_kernel<<<256, 256>>>(w, bias, ids, S);
    convert_x_kernel<<<128, 256>>>(x, N * (DIM / 4));

    static int smem_set = 0;
    if (!smem_set) {
        cudaFuncSetAttribute(gemm_f16_kernel,
                             cudaFuncAttributeMaxDynamicSharedMemorySize,
                             SM_TOTAL);
        smem_set = 1;
    }
    dim3 grid(N / BM, S / BN);
    gemm_f16_kernel<<<grid, 256, SM_TOTAL>>>((float*)d_out, N, S);

    long long base  = (long long)N * (long long)S;
    long long extra = (long long)out_size - base;
    if (extra > 0) {
        write_ids_kernel<<<(S + 255) / 256, 256>>>(ids, d_out, base, extra, S);
    }
}